// round 2
// baseline (speedup 1.0000x reference)
#include <cuda_runtime.h>
#include <math.h>

typedef unsigned long long u64;

// Problem constants: B=32, N=128, D=256, H=8, DK=32

// ---------------- scratch (static device globals; no allocation) -------------
__device__ float g_fA[1024 * 256];      // feats @ W_top
__device__ float g_fB[1024 * 256];      // feats @ W_bot
__device__ float g_conn[8 * 128 * 128]; // hard connection mask (0/1)
__device__ float g_h1[4096 * 256];      // gelu(x@W1+b1)
__device__ float g_xm[4096 * 256];      // mlp out
__device__ float g_q[4096 * 256];       // [B,H,N,DK]
__device__ float g_k[4096 * 256];
__device__ float g_v[4096 * 256];
__device__ float g_ao[4096 * 256];      // attention out, [B,N,D]

__device__ __forceinline__ float gelu_tanh(float x) {
    float x3 = x * x * x;
    float t = tanhf(0.7978845608028654f * (x + 0.044715f * x3));
    return 0.5f * x * (1.0f + t);
}

__device__ __forceinline__ u64 fma2(u64 a, u64 b, u64 c) {
    u64 d;
    asm("fma.rn.f32x2 %0, %1, %2, %3;" : "=l"(d) : "l"(a), "l"(b), "l"(c));
    return d;
}

// ---------------- SGEMM: C[M,256] = A[M,256] @ W[256,256] (+bias)(+gelu) -----
// 256 threads, BM=BN=64, BK=16, 4x4 per thread, packed f32x2 FMA (2x fp32 rate).
// gridDim.z selects among up to 3 (W, bias, C) triples (QKV fusion / fA+fB fusion).
// loadA_mode 1: gather A from memory_w layout: feats[h*128+n, d] = mw[n*2048 + h*256 + d]
// store_mode 1: QKV permute -> [B,H,N,DK]
__global__ void k_gemm(const float* __restrict__ A,
                       const float* __restrict__ W0, const float* __restrict__ W1,
                       const float* __restrict__ W2,
                       const float* __restrict__ b0, const float* __restrict__ b1,
                       const float* __restrict__ b2,
                       float* __restrict__ C0, float* __restrict__ C1, float* __restrict__ C2,
                       int act, int store_mode, int loadA_mode)
{
    __shared__ float As[16][68];    // [k][row], rows 16B-aligned (68*4=272)
    __shared__ float Wsd[16][128];  // [k][col pairs duplicated]: col j at floats {2j,2j+1}

    int z = blockIdx.z;
    const float* W    = (z == 0) ? W0 : (z == 1) ? W1 : W2;
    const float* bias = (z == 0) ? b0 : (z == 1) ? b1 : b2;
    float* C          = (z == 0) ? C0 : (z == 1) ? C1 : C2;

    int t = threadIdx.x;
    int tx = t & 15, ty = t >> 4;
    int rowBase = blockIdx.x * 64;
    int colBase = blockIdx.y * 64;

    int lak = t & 15;          // k index for A load
    int lar = (t >> 4) * 4;    // row base for A load
    int lwc = t & 63;          // col for W load
    int lwk = (t >> 6) * 4;    // k base for W load

    u64 acc[2][4];             // acc[ip][j]: rows (ty*4+2ip, +1), col tx*4+j
    #pragma unroll
    for (int i = 0; i < 2; i++)
        #pragma unroll
        for (int j = 0; j < 4; j++) acc[i][j] = 0ULL;

    for (int kt = 0; kt < 256; kt += 16) {
        if (loadA_mode == 0) {
            #pragma unroll
            for (int i = 0; i < 4; i++)
                As[lak][lar + i] = A[(rowBase + lar + i) * 256 + kt + lak];
        } else {
            #pragma unroll
            for (int i = 0; i < 4; i++) {
                int row = rowBase + lar + i;
                int h = row >> 7, n = row & 127;
                As[lak][lar + i] = A[n * 2048 + h * 256 + kt + lak];
            }
        }
        #pragma unroll
        for (int i = 0; i < 4; i++) {
            float w = W[(kt + lwk + i) * 256 + colBase + lwc];
            *(float2*)&Wsd[lwk + i][lwc * 2] = make_float2(w, w);
        }
        __syncthreads();

        #pragma unroll
        for (int kk = 0; kk < 16; kk++) {
            ulonglong2 pa  = *(const ulonglong2*)&As[kk][ty * 4];       // (r0,r1),(r2,r3)
            ulonglong2 pb0 = *(const ulonglong2*)&Wsd[kk][tx * 8];      // col j0 dup, j1 dup
            ulonglong2 pb1 = *(const ulonglong2*)&Wsd[kk][tx * 8 + 4];  // col j2 dup, j3 dup
            acc[0][0] = fma2(pa.x, pb0.x, acc[0][0]);
            acc[0][1] = fma2(pa.x, pb0.y, acc[0][1]);
            acc[0][2] = fma2(pa.x, pb1.x, acc[0][2]);
            acc[0][3] = fma2(pa.x, pb1.y, acc[0][3]);
            acc[1][0] = fma2(pa.y, pb0.x, acc[1][0]);
            acc[1][1] = fma2(pa.y, pb0.y, acc[1][1]);
            acc[1][2] = fma2(pa.y, pb1.x, acc[1][2]);
            acc[1][3] = fma2(pa.y, pb1.y, acc[1][3]);
        }
        __syncthreads();
    }

    #pragma unroll
    for (int ip = 0; ip < 2; ip++) {
        #pragma unroll
        for (int j = 0; j < 4; j++) {
            float lo, hi;
            asm("mov.b64 {%0, %1}, %2;" : "=f"(lo), "=f"(hi) : "l"(acc[ip][j]));
            int col = colBase + tx * 4 + j;
            float bv = bias ? bias[col] : 0.0f;
            float v0 = lo + bv, v1 = hi + bv;
            if (act) { v0 = gelu_tanh(v0); v1 = gelu_tanh(v1); }
            int row0 = rowBase + ty * 4 + ip * 2;
            if (store_mode == 0) {
                C[row0 * 256 + col] = v0;
                C[(row0 + 1) * 256 + col] = v1;
            } else {
                int h = col >> 5, dk = col & 31;
                int b0r = row0 >> 7, n0 = row0 & 127;
                int b1r = (row0 + 1) >> 7, n1 = (row0 + 1) & 127;
                C[(((b0r * 8 + h) * 128 + n0) * 32) + dk] = v0;
                C[(((b1r * 8 + h) * 128 + n1) * 32) + dk] = v1;
            }
        }
    }
}

// ---------------- connection mask, tiled, no reductions ----------------------
// Block = (h, 16 i's, 32 j's), 128 threads; thread owns 2i x 2j pairs fully.
// logits[h,i,j,k] = sum_d relu(fA[h,j,d]+fB[h,i,d]+ob[d]) * cw[d,k] + cb[k]
// conn = (l1+g1 > l0+g0)
__global__ void k_conn(const float* __restrict__ fA, const float* __restrict__ fB,
                       const float* __restrict__ ob, const float* __restrict__ cw,
                       const float* __restrict__ cb, const float* __restrict__ gu,
                       float* __restrict__ conn)
{
    __shared__ float Aj[32][33];
    __shared__ float Bi[16][33];
    __shared__ float Cs0[256], Cs1[256];

    int h = blockIdx.x;
    int ibase = blockIdx.y * 16;
    int jbase = blockIdx.z * 32;
    int t = threadIdx.x;          // 128
    int tx = t & 15, ty = t >> 4; // tx -> j pair, ty -> i pair

    for (int d = t; d < 256; d += 128) {
        Cs0[d] = cw[2 * d];
        Cs1[d] = cw[2 * d + 1];
    }

    float l0[2][2] = {{0.f, 0.f}, {0.f, 0.f}};
    float l1[2][2] = {{0.f, 0.f}, {0.f, 0.f}};

    for (int d0 = 0; d0 < 256; d0 += 32) {
        __syncthreads();  // also covers Cs0/Cs1 on first pass
        // stage fA chunk: 32 j x 32 d
        #pragma unroll
        for (int u = 0; u < 2; u++) {
            int s = t * 2 + u;
            int j = s >> 3, c = (s & 7) * 4;
            float4 v = *(const float4*)&fA[(h * 128 + jbase + j) * 256 + d0 + c];
            Aj[j][c] = v.x; Aj[j][c + 1] = v.y; Aj[j][c + 2] = v.z; Aj[j][c + 3] = v.w;
        }
        // stage fB chunk (+ob): 16 i x 32 d
        {
            int i = t >> 3, c = (t & 7) * 4;
            float4 v = *(const float4*)&fB[(h * 128 + ibase + i) * 256 + d0 + c];
            float4 o = *(const float4*)&ob[d0 + c];
            Bi[i][c] = v.x + o.x; Bi[i][c + 1] = v.y + o.y;
            Bi[i][c + 2] = v.z + o.z; Bi[i][c + 3] = v.w + o.w;
        }
        __syncthreads();

        #pragma unroll
        for (int dd = 0; dd < 32; dd++) {
            float a0 = Aj[tx * 2][dd], a1 = Aj[tx * 2 + 1][dd];
            float b0 = Bi[ty * 2][dd], b1 = Bi[ty * 2 + 1][dd];
            float c0v = Cs0[d0 + dd], c1v = Cs1[d0 + dd];
            float r00 = fmaxf(a0 + b0, 0.f), r10 = fmaxf(a1 + b0, 0.f);
            float r01 = fmaxf(a0 + b1, 0.f), r11 = fmaxf(a1 + b1, 0.f);
            l0[0][0] = fmaf(r00, c0v, l0[0][0]); l1[0][0] = fmaf(r00, c1v, l1[0][0]);
            l0[0][1] = fmaf(r10, c0v, l0[0][1]); l1[0][1] = fmaf(r10, c1v, l1[0][1]);
            l0[1][0] = fmaf(r01, c0v, l0[1][0]); l1[1][0] = fmaf(r01, c1v, l1[1][0]);
            l0[1][1] = fmaf(r11, c0v, l0[1][1]); l1[1][1] = fmaf(r11, c1v, l1[1][1]);
        }
    }

    float cb0 = cb[0], cb1 = cb[1];
    #pragma unroll
    for (int ii = 0; ii < 2; ii++) {
        int i = ibase + ty * 2 + ii;
        #pragma unroll
        for (int jj = 0; jj < 2; jj++) {
            int j = jbase + tx * 2 + jj;
            int idx = (h * 128 + i) * 128 + j;
            float2 u2 = *(const float2*)&gu[idx * 2];
            float g0 = -logf(-logf(u2.x + 1e-10f) + 1e-10f);
            float g1 = -logf(-logf(u2.y + 1e-10f) + 1e-10f);
            conn[idx] = ((l1[ii][jj] + cb1 + g1) > (l0[ii][jj] + cb0 + g0)) ? 1.0f : 0.0f;
        }
    }
}

// ---------------- masked attention, one block per (b,h), 128 threads ---------
#define SC_FLOATS (128 * 129)
#define KV_FLOATS (128 * 32)
#define SMEM_ATTN ((SC_FLOATS + KV_FLOATS) * 4 + 128 * 4 * 4)

__global__ void k_attn(const float* __restrict__ q, const float* __restrict__ k,
                       const float* __restrict__ v, const float* __restrict__ conn,
                       float* __restrict__ ao)
{
    extern __shared__ float sm[];
    float* sc = sm;                       // 128*129
    float* kv = sm + SC_FLOATS;           // 128*32
    unsigned* cmask = (unsigned*)(kv + KV_FLOATS);  // 128*4 words

    int bid = blockIdx.x;
    int b = bid >> 3, h = bid & 7;
    int t = threadIdx.x, w = t >> 5, lane = t & 31;

    const float* cr = conn + h * 16384;
    for (int i0 = 0; i0 < 128; i0++) {
        float c = cr[i0 * 128 + t];
        unsigned bal = __ballot_sync(0xffffffffu, c > 0.5f);
        if (lane == 0) cmask[i0 * 4 + w] = bal;
    }

    for (int idx = t; idx < KV_FLOATS; idx += 128) kv[idx] = k[bid * 4096 + idx];
    __syncthreads();

    float4 qr[8];
    const float4* qp = (const float4*)(q + (bid * 128 + t) * 32);
    #pragma unroll
    for (int d = 0; d < 8; d++) qr[d] = qp[d];

    unsigned marr[4];
    #pragma unroll
    for (int u = 0; u < 4; u++) marr[u] = cmask[t * 4 + u];

    const float scale = 0.17677669529663687f;  // 1/sqrt(32)
    const float4* kv4 = (const float4*)kv;
    float mx = -INFINITY;

    for (int wdx = 0; wdx < 4; wdx++) {
        unsigned word = marr[wdx];
        for (int jj = 0; jj < 32; jj++) {
            int j = (wdx << 5) | jj;
            float s;
            if ((word >> jj) & 1u) {
                float a0 = 0.f, a1 = 0.f, a2 = 0.f, a3 = 0.f;
                #pragma unroll
                for (int d = 0; d < 8; d++) {
                    float4 kk4 = kv4[j * 8 + d];
                    a0 = fmaf(qr[d].x, kk4.x, a0);
                    a1 = fmaf(qr[d].y, kk4.y, a1);
                    a2 = fmaf(qr[d].z, kk4.z, a2);
                    a3 = fmaf(qr[d].w, kk4.w, a3);
                }
                s = ((a0 + a1) + (a2 + a3)) * scale;
                mx = fmaxf(mx, s);
            } else {
                s = -INFINITY;
            }
            sc[t * 129 + j] = s;
        }
    }
    __syncthreads();

    for (int idx = t; idx < KV_FLOATS; idx += 128) kv[idx] = v[bid * 4096 + idx];

    float sum = 0.0f;
    for (int j = 0; j < 128; j++) {
        float e = expf(sc[t * 129 + j] - mx);
        sum += e;
        sc[t * 129 + j] = e;
    }
    float inv = 1.0f / sum;
    __syncthreads();

    float acc[32];
    #pragma unroll
    for (int d = 0; d < 32; d++) acc[d] = 0.0f;

    for (int j = 0; j < 128; j++) {
        float p = sc[t * 129 + j];
        #pragma unroll
        for (int dd = 0; dd < 8; dd++) {
            float4 vv = kv4[j * 8 + dd];
            acc[dd * 4 + 0] = fmaf(p, vv.x, acc[dd * 4 + 0]);
            acc[dd * 4 + 1] = fmaf(p, vv.y, acc[dd * 4 + 1]);
            acc[dd * 4 + 2] = fmaf(p, vv.z, acc[dd * 4 + 2]);
            acc[dd * 4 + 3] = fmaf(p, vv.w, acc[dd * 4 + 3]);
        }
    }

    float* op = ao + (b * 128 + t) * 256 + h * 32;
    #pragma unroll
    for (int d = 0; d < 32; d++) op[d] = acc[d] * inv;
}

// ---------------- launch ------------------------------------------------------
extern "C" void kernel_launch(void* const* d_in, const int* in_sizes, int n_in,
                              void* d_out, int out_size)
{
    const float* x        = (const float*)d_in[0];
    const float* gumbel_u = (const float*)d_in[1];
    const float* memory_w = (const float*)d_in[2];
    const float* fc_out_w = (const float*)d_in[3];
    const float* fc_out_b = (const float*)d_in[4];
    const float* fc_cat_w = (const float*)d_in[5];
    const float* fc_cat_b = (const float*)d_in[6];
    const float* wq       = (const float*)d_in[7];
    const float* bq       = (const float*)d_in[8];
    const float* wk       = (const float*)d_in[9];
    const float* bk       = (const float*)d_in[10];
    const float* wv       = (const float*)d_in[11];
    const float* bv       = (const float*)d_in[12];
    const float* out_w    = (const float*)d_in[13];
    const float* out_b    = (const float*)d_in[14];
    const float* mlp_w1   = (const float*)d_in[15];
    const float* mlp_b1   = (const float*)d_in[16];
    const float* mlp_w2   = (const float*)d_in[17];
    const float* mlp_b2   = (const float*)d_in[18];

    float *fA, *fB, *conn, *h1, *xm, *q, *k, *v, *ao;
    cudaGetSymbolAddress((void**)&fA, g_fA);
    cudaGetSymbolAddress((void**)&fB, g_fB);
    cudaGetSymbolAddress((void**)&conn, g_conn);
    cudaGetSymbolAddress((void**)&h1, g_h1);
    cudaGetSymbolAddress((void**)&xm, g_xm);
    cudaGetSymbolAddress((void**)&q, g_q);
    cudaGetSymbolAddress((void**)&k, g_k);
    cudaGetSymbolAddress((void**)&v, g_v);
    cudaGetSymbolAddress((void**)&ao, g_ao);

    cudaFuncSetAttribute(k_attn, cudaFuncAttributeMaxDynamicSharedMemorySize, SMEM_ATTN);

    // mask branch: fA/fB in one fused launch (A gathered from memory_w layout)
    k_gemm<<<dim3(16, 4, 2), 256>>>(memory_w,
                                    fc_out_w, fc_out_w + 256 * 256, nullptr,
                                    nullptr, nullptr, nullptr,
                                    fA, fB, nullptr,
                                    0, 0, 1);
    k_conn<<<dim3(8, 8, 4), 128>>>(fA, fB, fc_out_b, fc_cat_w, fc_cat_b, gumbel_u, conn);

    // MLP
    k_gemm<<<dim3(64, 4, 1), 256>>>(x, mlp_w1, nullptr, nullptr,
                                    mlp_b1, nullptr, nullptr,
                                    h1, nullptr, nullptr, 1, 0, 0);
    k_gemm<<<dim3(64, 4, 1), 256>>>(h1, mlp_w2, nullptr, nullptr,
                                    mlp_b2, nullptr, nullptr,
                                    xm, nullptr, nullptr, 0, 0, 0);

    // QKV fused (permuted store to [B,H,N,DK])
    k_gemm<<<dim3(64, 4, 3), 256>>>(xm, wq, wk, wv,
                                    bq, bk, bv,
                                    q, k, v, 0, 1, 0);

    // masked attention
    k_attn<<<256, 128, SMEM_ATTN>>>(q, k, v, conn, ao);

    // output projection straight into d_out
    k_gemm<<<dim3(64, 4, 1), 256>>>(ao, out_w, nullptr, nullptr,
                                    out_b, nullptr, nullptr,
                                    (float*)d_out, nullptr, nullptr, 0, 0, 0);
}

// round 3
// speedup vs baseline: 2.5866x; 2.5866x over previous
#include <cuda_runtime.h>
#include <cuda_bf16.h>
#include <math.h>

// Problem constants: B=32, N=128, D=256, H=8, DK=32
typedef unsigned int u32;

// ---------------- scratch (static device globals; no allocation) -------------
__device__ __align__(16) float g_fA[1024 * 256];
__device__ __align__(16) float g_fB[1024 * 256];
__device__ __align__(16) float g_conn[8 * 128 * 128];
__device__ __align__(16) float g_q[4096 * 256];     // [B,H,N,DK]
__device__ __align__(16) float g_k[4096 * 256];
__device__ __align__(16) float g_v[4096 * 256];

// bf16 split planes
__device__ __align__(16) __nv_bfloat16 g_whi[8 * 65536];  // weights: mlp1,mlp2,q,k,v,out,fcA,fcB
__device__ __align__(16) __nv_bfloat16 g_wlo[8 * 65536];
__device__ __align__(16) __nv_bfloat16 g_xhi[4096 * 256];
__device__ __align__(16) __nv_bfloat16 g_xlo[4096 * 256];
__device__ __align__(16) __nv_bfloat16 g_fthi[1024 * 256];  // feats
__device__ __align__(16) __nv_bfloat16 g_ftlo[1024 * 256];
__device__ __align__(16) __nv_bfloat16 g_h1hi[4096 * 256];
__device__ __align__(16) __nv_bfloat16 g_h1lo[4096 * 256];
__device__ __align__(16) __nv_bfloat16 g_xmhi[4096 * 256];
__device__ __align__(16) __nv_bfloat16 g_xmlo[4096 * 256];
__device__ __align__(16) __nv_bfloat16 g_aohi[4096 * 256];
__device__ __align__(16) __nv_bfloat16 g_aolo[4096 * 256];

__device__ __forceinline__ float gelu_tanh(float x) {
    float x3 = x * x * x;
    float t = tanhf(0.7978845608028654f * (x + 0.044715f * x3));
    return 0.5f * x * (1.0f + t);
}

__device__ __forceinline__ void split_bf16(float v, __nv_bfloat16& h, __nv_bfloat16& l) {
    h = __float2bfloat16_rn(v);
    l = __float2bfloat16_rn(v - __bfloat162float(h));
}

#define LDSM4(r, addr)                                                        \
    asm volatile("ldmatrix.sync.aligned.m8n8.x4.shared.b16 {%0,%1,%2,%3}, [%4];" \
                 : "=r"(r[0]), "=r"(r[1]), "=r"(r[2]), "=r"(r[3]) : "r"(addr))

#define LDSM4T(r, addr)                                                       \
    asm volatile("ldmatrix.sync.aligned.m8n8.x4.trans.shared.b16 {%0,%1,%2,%3}, [%4];" \
                 : "=r"(r[0]), "=r"(r[1]), "=r"(r[2]), "=r"(r[3]) : "r"(addr))

#define MMA16816(d, a, b)                                                     \
    asm volatile("mma.sync.aligned.m16n8k16.row.col.f32.bf16.bf16.f32 "       \
                 "{%0,%1,%2,%3}, {%4,%5,%6,%7}, {%8,%9}, {%0,%1,%2,%3};"      \
                 : "+f"(d[0]), "+f"(d[1]), "+f"(d[2]), "+f"(d[3])             \
                 : "r"(a[0]), "r"(a[1]), "r"(a[2]), "r"(a[3]),                \
                   "r"(b[0]), "r"(b[1]))

// ---------------- convert weights to bf16 hi/lo planes -----------------------
struct WPtrs { const float* p[8]; };

__global__ void k_cvtW(WPtrs P) {
    int wy = blockIdx.y;
    const float* src = P.p[wy];
    int t = threadIdx.x;
    int base = blockIdx.x * 2048;
    #pragma unroll
    for (int i = 0; i < 8; i++) {
        int idx = base + i * 256 + t;
        __nv_bfloat16 h, l;
        split_bf16(src[idx], h, l);
        g_whi[wy * 65536 + idx] = h;
        g_wlo[wy * 65536 + idx] = l;
    }
}

// ---------------- convert activation fp32 -> bf16 planes ---------------------
// gather=1: feats layout (row = h*128+n <- mw[n*2048 + h*256 + d])
__global__ void k_cvtA(const float* __restrict__ src, __nv_bfloat16* __restrict__ hi,
                       __nv_bfloat16* __restrict__ lo, int gather) {
    int row = blockIdx.x;
    int t = threadIdx.x;
    float v;
    if (gather) {
        int h = row >> 7, n = row & 127;
        v = src[n * 2048 + h * 256 + t];
    } else {
        v = src[row * 256 + t];
    }
    __nv_bfloat16 hh, ll;
    split_bf16(v, hh, ll);
    hi[row * 256 + t] = hh;
    lo[row * 256 + t] = ll;
}

// ---------------- tensor-core GEMM: C[M,256] = A[M,256] @ W[256,256] ---------
// Split-bf16 (3 MMAs): A = Ahi+Alo, W = Whi+Wlo; acc += AhWh + AhWl + AlWh.
// 256 threads = 8 warps (4 x 2), BM=128, BN=64, BK=32, warp tile 32x32.
// mode 0: fp32 C[row*256+col] (+bias)
// mode 1: bf16 hi/lo plane outputs (+bias, +optional gelu)
// mode 2: fp32 QKV permute -> [B,H,N,DK] (+bias)
__global__ void __launch_bounds__(256, 1)
k_mma(const __nv_bfloat16* __restrict__ Ahi, const __nv_bfloat16* __restrict__ Alo,
      const float* __restrict__ b0, const float* __restrict__ b1, const float* __restrict__ b2,
      float* __restrict__ C0, float* __restrict__ C1, float* __restrict__ C2,
      __nv_bfloat16* __restrict__ Chi, __nv_bfloat16* __restrict__ Clo,
      int wOff0, int act, int mode)
{
    // padded smem: A rows 40 bf16 (80B stride), W rows 72 bf16 (144B stride)
    __shared__ __nv_bfloat16 sAhi[128 * 40];
    __shared__ __nv_bfloat16 sAlo[128 * 40];
    __shared__ __nv_bfloat16 sWhi[32 * 72];
    __shared__ __nv_bfloat16 sWlo[32 * 72];

    int z = blockIdx.z;
    const __nv_bfloat16* Wh = g_whi + (size_t)(wOff0 + z) * 65536;
    const __nv_bfloat16* Wl = g_wlo + (size_t)(wOff0 + z) * 65536;
    const float* bias = (z == 0) ? b0 : (z == 1) ? b1 : b2;
    float* Cf = (z == 0) ? C0 : (z == 1) ? C1 : C2;

    int t = threadIdx.x;
    int warp = t >> 5, lane = t & 31;
    int wm = warp >> 1, wn = warp & 1;
    int rowBase = blockIdx.x * 128;
    int colBase = blockIdx.y * 64;

    u32 sAhiB = (u32)__cvta_generic_to_shared(sAhi);
    u32 sAloB = (u32)__cvta_generic_to_shared(sAlo);
    u32 sWhiB = (u32)__cvta_generic_to_shared(sWhi);
    u32 sWloB = (u32)__cvta_generic_to_shared(sWlo);

    int g = lane >> 3, r = lane & 7;

    float acc[2][4][4];
    #pragma unroll
    for (int mt = 0; mt < 2; mt++)
        #pragma unroll
        for (int nt = 0; nt < 4; nt++)
            #pragma unroll
            for (int i = 0; i < 4; i++) acc[mt][nt][i] = 0.0f;

    for (int kt = 0; kt < 256; kt += 32) {
        // stage A: 128 x 32 per plane, 16B chunks (8 bf16)
        #pragma unroll
        for (int u = 0; u < 2; u++) {
            int c = t + u * 256;
            int row = c >> 2, ch = c & 3;
            int gidx = (rowBase + row) * 256 + kt + ch * 8;
            int soff = row * 40 + ch * 8;
            *(uint4*)&sAhi[soff] = *(const uint4*)&Ahi[gidx];
            *(uint4*)&sAlo[soff] = *(const uint4*)&Alo[gidx];
        }
        // stage W: 32 x 64 per plane
        {
            int row = t >> 3, ch = t & 7;
            int gidx = (kt + row) * 256 + colBase + ch * 8;
            int soff = row * 72 + ch * 8;
            *(uint4*)&sWhi[soff] = *(const uint4*)&Wh[gidx];
            *(uint4*)&sWlo[soff] = *(const uint4*)&Wl[gidx];
        }
        __syncthreads();

        #pragma unroll
        for (int ks = 0; ks < 32; ks += 16) {
            u32 ah[2][4], al[2][4], bh[2][4], bl[2][4];
            #pragma unroll
            for (int mt = 0; mt < 2; mt++) {
                int rowA = wm * 32 + mt * 16 + r + ((g & 1) << 3);
                int kcol = ks + ((g >> 1) << 3);
                u32 off = (u32)(rowA * 40 + kcol) * 2;
                LDSM4(ah[mt], sAhiB + off);
                LDSM4(al[mt], sAloB + off);
            }
            #pragma unroll
            for (int np = 0; np < 2; np++) {
                int krow = ks + r + ((g & 1) << 3);
                int ncol = wn * 32 + np * 16 + ((g >> 1) << 3);
                u32 off = (u32)(krow * 72 + ncol) * 2;
                LDSM4T(bh[np], sWhiB + off);
                LDSM4T(bl[np], sWloB + off);
            }
            #pragma unroll
            for (int mt = 0; mt < 2; mt++) {
                #pragma unroll
                for (int nt = 0; nt < 4; nt++) {
                    const u32* Bh = &bh[nt >> 1][(nt & 1) * 2];
                    const u32* Bl = &bl[nt >> 1][(nt & 1) * 2];
                    MMA16816(acc[mt][nt], ah[mt], Bh);
                    MMA16816(acc[mt][nt], ah[mt], Bl);
                    MMA16816(acc[mt][nt], al[mt], Bh);
                }
            }
        }
        __syncthreads();
    }

    // ---------------- epilogue ----------------
    #pragma unroll
    for (int mt = 0; mt < 2; mt++) {
        #pragma unroll
        for (int nt = 0; nt < 4; nt++) {
            int row0 = rowBase + wm * 32 + mt * 16 + (lane >> 2);
            int col0 = colBase + wn * 32 + nt * 8 + (lane & 3) * 2;
            float bv0 = bias ? bias[col0] : 0.0f;
            float bv1 = bias ? bias[col0 + 1] : 0.0f;
            #pragma unroll
            for (int half = 0; half < 2; half++) {
                int row = row0 + half * 8;
                float v0 = acc[mt][nt][half * 2 + 0] + bv0;
                float v1 = acc[mt][nt][half * 2 + 1] + bv1;
                if (act) { v0 = gelu_tanh(v0); v1 = gelu_tanh(v1); }
                if (mode == 0) {
                    *(float2*)&Cf[row * 256 + col0] = make_float2(v0, v1);
                } else if (mode == 1) {
                    __nv_bfloat16 h0, l0, h1, l1;
                    split_bf16(v0, h0, l0);
                    split_bf16(v1, h1, l1);
                    __nv_bfloat162 H; H.x = h0; H.y = h1;
                    __nv_bfloat162 L; L.x = l0; L.y = l1;
                    *(__nv_bfloat162*)&Chi[row * 256 + col0] = H;
                    *(__nv_bfloat162*)&Clo[row * 256 + col0] = L;
                } else {
                    int b = row >> 7, n = row & 127;
                    int h = col0 >> 5, dk = col0 & 31;
                    *(float2*)&Cf[(((b * 8 + h) * 128 + n) * 32) + dk] = make_float2(v0, v1);
                }
            }
        }
    }
}

// ---------------- connection mask, tiled, no reductions ----------------------
__global__ void k_conn(const float* __restrict__ fA, const float* __restrict__ fB,
                       const float* __restrict__ ob, const float* __restrict__ cw,
                       const float* __restrict__ cb, const float* __restrict__ gu,
                       float* __restrict__ conn)
{
    __shared__ float Aj[32][33];
    __shared__ float Bi[16][33];
    __shared__ float Cs0[256], Cs1[256];

    int h = blockIdx.x;
    int ibase = blockIdx.y * 16;
    int jbase = blockIdx.z * 32;
    int t = threadIdx.x;          // 128
    int tx = t & 15, ty = t >> 4;

    for (int d = t; d < 256; d += 128) {
        Cs0[d] = cw[2 * d];
        Cs1[d] = cw[2 * d + 1];
    }

    float l0[2][2] = {{0.f, 0.f}, {0.f, 0.f}};
    float l1[2][2] = {{0.f, 0.f}, {0.f, 0.f}};

    for (int d0 = 0; d0 < 256; d0 += 32) {
        __syncthreads();
        #pragma unroll
        for (int u = 0; u < 2; u++) {
            int s = t * 2 + u;
            int j = s >> 3, c = (s & 7) * 4;
            float4 v = *(const float4*)&fA[(h * 128 + jbase + j) * 256 + d0 + c];
            Aj[j][c] = v.x; Aj[j][c + 1] = v.y; Aj[j][c + 2] = v.z; Aj[j][c + 3] = v.w;
        }
        {
            int i = t >> 3, c = (t & 7) * 4;
            float4 v = *(const float4*)&fB[(h * 128 + ibase + i) * 256 + d0 + c];
            float4 o = *(const float4*)&ob[d0 + c];
            Bi[i][c] = v.x + o.x; Bi[i][c + 1] = v.y + o.y;
            Bi[i][c + 2] = v.z + o.z; Bi[i][c + 3] = v.w + o.w;
        }
        __syncthreads();

        #pragma unroll
        for (int dd = 0; dd < 32; dd++) {
            float a0 = Aj[tx * 2][dd], a1 = Aj[tx * 2 + 1][dd];
            float b0 = Bi[ty * 2][dd], b1 = Bi[ty * 2 + 1][dd];
            float c0v = Cs0[d0 + dd], c1v = Cs1[d0 + dd];
            float r00 = fmaxf(a0 + b0, 0.f), r10 = fmaxf(a1 + b0, 0.f);
            float r01 = fmaxf(a0 + b1, 0.f), r11 = fmaxf(a1 + b1, 0.f);
            l0[0][0] = fmaf(r00, c0v, l0[0][0]); l1[0][0] = fmaf(r00, c1v, l1[0][0]);
            l0[0][1] = fmaf(r10, c0v, l0[0][1]); l1[0][1] = fmaf(r10, c1v, l1[0][1]);
            l0[1][0] = fmaf(r01, c0v, l0[1][0]); l1[1][0] = fmaf(r01, c1v, l1[1][0]);
            l0[1][1] = fmaf(r11, c0v, l0[1][1]); l1[1][1] = fmaf(r11, c1v, l1[1][1]);
        }
    }

    float cb0 = cb[0], cb1 = cb[1];
    #pragma unroll
    for (int ii = 0; ii < 2; ii++) {
        int i = ibase + ty * 2 + ii;
        #pragma unroll
        for (int jj = 0; jj < 2; jj++) {
            int j = jbase + tx * 2 + jj;
            int idx = (h * 128 + i) * 128 + j;
            float2 u2 = *(const float2*)&gu[idx * 2];
            float g0 = -logf(-logf(u2.x + 1e-10f) + 1e-10f);
            float g1 = -logf(-logf(u2.y + 1e-10f) + 1e-10f);
            conn[idx] = ((l1[ii][jj] + cb1 + g1) > (l0[ii][jj] + cb0 + g0)) ? 1.0f : 0.0f;
        }
    }
}

// ---------------- masked attention, one block per (b,h), 128 threads ---------
#define SC_FLOATS (128 * 129)
#define KV_FLOATS (128 * 32)
#define SMEM_ATTN ((SC_FLOATS + KV_FLOATS) * 4 + 128 * 4 * 4)

__global__ void k_attn(const float* __restrict__ q, const float* __restrict__ k,
                       const float* __restrict__ v, const float* __restrict__ conn,
                       __nv_bfloat16* __restrict__ aohi, __nv_bfloat16* __restrict__ aolo)
{
    extern __shared__ float sm[];
    float* sc = sm;                       // 128*129
    float* kv = sm + SC_FLOATS;           // 128*32
    unsigned* cmask = (unsigned*)(kv + KV_FLOATS);

    int bid = blockIdx.x;
    int b = bid >> 3, h = bid & 7;
    int t = threadIdx.x, w = t >> 5, lane = t & 31;

    const float* cr = conn + h * 16384;
    for (int i0 = 0; i0 < 128; i0++) {
        float c = cr[i0 * 128 + t];
        unsigned bal = __ballot_sync(0xffffffffu, c > 0.5f);
        if (lane == 0) cmask[i0 * 4 + w] = bal;
    }

    for (int idx = t; idx < KV_FLOATS; idx += 128) kv[idx] = k[bid * 4096 + idx];
    __syncthreads();

    float4 qr[8];
    const float4* qp = (const float4*)(q + (bid * 128 + t) * 32);
    #pragma unroll
    for (int d = 0; d < 8; d++) qr[d] = qp[d];

    unsigned marr[4];
    #pragma unroll
    for (int u = 0; u < 4; u++) marr[u] = cmask[t * 4 + u];

    const float scale = 0.17677669529663687f;  // 1/sqrt(32)
    const float4* kv4 = (const float4*)kv;
    float mx = -INFINITY;

    for (int wdx = 0; wdx < 4; wdx++) {
        unsigned word = marr[wdx];
        for (int jj = 0; jj < 32; jj++) {
            int j = (wdx << 5) | jj;
            float s;
            if ((word >> jj) & 1u) {
                float a0 = 0.f, a1 = 0.f, a2 = 0.f, a3 = 0.f;
                #pragma unroll
                for (int d = 0; d < 8; d++) {
                    float4 kk4 = kv4[j * 8 + d];
                    a0 = fmaf(qr[d].x, kk4.x, a0);
                    a1 = fmaf(qr[d].y, kk4.y, a1);
                    a2 = fmaf(qr[d].z, kk4.z, a2);
                    a3 = fmaf(qr[d].w, kk4.w, a3);
                }
                s = ((a0 + a1) + (a2 + a3)) * scale;
                mx = fmaxf(mx, s);
            } else {
                s = -INFINITY;
            }
            sc[t * 129 + j] = s;
        }
    }
    __syncthreads();

    for (int idx = t; idx < KV_FLOATS; idx += 128) kv[idx] = v[bid * 4096 + idx];

    float sum = 0.0f;
    for (int j = 0; j < 128; j++) {
        float e = expf(sc[t * 129 + j] - mx);
        sum += e;
        sc[t * 129 + j] = e;
    }
    float inv = 1.0f / sum;
    __syncthreads();

    float acc[32];
    #pragma unroll
    for (int d = 0; d < 32; d++) acc[d] = 0.0f;

    for (int j = 0; j < 128; j++) {
        float p = sc[t * 129 + j];
        #pragma unroll
        for (int dd = 0; dd < 8; dd++) {
            float4 vv = kv4[j * 8 + dd];
            acc[dd * 4 + 0] = fmaf(p, vv.x, acc[dd * 4 + 0]);
            acc[dd * 4 + 1] = fmaf(p, vv.y, acc[dd * 4 + 1]);
            acc[dd * 4 + 2] = fmaf(p, vv.z, acc[dd * 4 + 2]);
            acc[dd * 4 + 3] = fmaf(p, vv.w, acc[dd * 4 + 3]);
        }
    }

    int obase = (b * 128 + t) * 256 + h * 32;
    #pragma unroll
    for (int d = 0; d < 32; d += 2) {
        float v0 = acc[d] * inv, v1 = acc[d + 1] * inv;
        __nv_bfloat16 h0, l0, h1, l1;
        split_bf16(v0, h0, l0);
        split_bf16(v1, h1, l1);
        __nv_bfloat162 H; H.x = h0; H.y = h1;
        __nv_bfloat162 L; L.x = l0; L.y = l1;
        *(__nv_bfloat162*)&aohi[obase + d] = H;
        *(__nv_bfloat162*)&aolo[obase + d] = L;
    }
}

// ---------------- launch ------------------------------------------------------
extern "C" void kernel_launch(void* const* d_in, const int* in_sizes, int n_in,
                              void* d_out, int out_size)
{
    const float* x        = (const float*)d_in[0];
    const float* gumbel_u = (const float*)d_in[1];
    const float* memory_w = (const float*)d_in[2];
    const float* fc_out_w = (const float*)d_in[3];
    const float* fc_out_b = (const float*)d_in[4];
    const float* fc_cat_w = (const float*)d_in[5];
    const float* fc_cat_b = (const float*)d_in[6];
    const float* wq       = (const float*)d_in[7];
    const float* bq       = (const float*)d_in[8];
    const float* wk       = (const float*)d_in[9];
    const float* bk       = (const float*)d_in[10];
    const float* wv       = (const float*)d_in[11];
    const float* bv       = (const float*)d_in[12];
    const float* out_w    = (const float*)d_in[13];
    const float* out_b    = (const float*)d_in[14];
    const float* mlp_w1   = (const float*)d_in[15];
    const float* mlp_b1   = (const float*)d_in[16];
    const float* mlp_w2   = (const float*)d_in[17];
    const float* mlp_b2   = (const float*)d_in[18];

    float *fA, *fB, *conn, *q, *k, *v;
    cudaGetSymbolAddress((void**)&fA, g_fA);
    cudaGetSymbolAddress((void**)&fB, g_fB);
    cudaGetSymbolAddress((void**)&conn, g_conn);
    cudaGetSymbolAddress((void**)&q, g_q);
    cudaGetSymbolAddress((void**)&k, g_k);
    cudaGetSymbolAddress((void**)&v, g_v);

    __nv_bfloat16 *xhi, *xlo, *fthi, *ftlo, *h1hi, *h1lo, *xmhi, *xmlo, *aohi, *aolo;
    cudaGetSymbolAddress((void**)&xhi, g_xhi);
    cudaGetSymbolAddress((void**)&xlo, g_xlo);
    cudaGetSymbolAddress((void**)&fthi, g_fthi);
    cudaGetSymbolAddress((void**)&ftlo, g_ftlo);
    cudaGetSymbolAddress((void**)&h1hi, g_h1hi);
    cudaGetSymbolAddress((void**)&h1lo, g_h1lo);
    cudaGetSymbolAddress((void**)&xmhi, g_xmhi);
    cudaGetSymbolAddress((void**)&xmlo, g_xmlo);
    cudaGetSymbolAddress((void**)&aohi, g_aohi);
    cudaGetSymbolAddress((void**)&aolo, g_aolo);

    cudaFuncSetAttribute(k_attn, cudaFuncAttributeMaxDynamicSharedMemorySize, SMEM_ATTN);

    // weight planes: [0]=mlp_w1 [1]=mlp_w2 [2]=wq [3]=wk [4]=wv [5]=out_w [6]=fcA [7]=fcB
    WPtrs P;
    P.p[0] = mlp_w1; P.p[1] = mlp_w2; P.p[2] = wq; P.p[3] = wk;
    P.p[4] = wv; P.p[5] = out_w; P.p[6] = fc_out_w; P.p[7] = fc_out_w + 65536;
    k_cvtW<<<dim3(32, 8), 256>>>(P);

    // activation planes
    k_cvtA<<<4096, 256>>>(x, xhi, xlo, 0);
    k_cvtA<<<1024, 256>>>(memory_w, fthi, ftlo, 1);

    // mask branch: fA/fB fused (z=2)
    k_mma<<<dim3(8, 4, 2), 256>>>(fthi, ftlo,
                                  nullptr, nullptr, nullptr,
                                  fA, fB, nullptr, nullptr, nullptr,
                                  6, 0, 0);
    k_conn<<<dim3(8, 8, 4), 128>>>(fA, fB, fc_out_b, fc_cat_w, fc_cat_b, gumbel_u, conn);

    // MLP (bf16 plane outputs)
    k_mma<<<dim3(32, 4, 1), 256>>>(xhi, xlo,
                                   mlp_b1, nullptr, nullptr,
                                   nullptr, nullptr, nullptr, h1hi, h1lo,
                                   0, 1, 1);
    k_mma<<<dim3(32, 4, 1), 256>>>(h1hi, h1lo,
                                   mlp_b2, nullptr, nullptr,
                                   nullptr, nullptr, nullptr, xmhi, xmlo,
                                   1, 0, 1);

    // QKV fused (z=3, permuted fp32 out)
    k_mma<<<dim3(32, 4, 3), 256>>>(xmhi, xmlo,
                                   bq, bk, bv,
                                   q, k, v, nullptr, nullptr,
                                   2, 0, 2);

    // masked attention -> ao planes
    k_attn<<<256, 128, SMEM_ATTN>>>(q, k, v, conn, aohi, aolo);

    // output projection -> d_out (fp32)
    k_mma<<<dim3(32, 4, 1), 256>>>(aohi, aolo,
                                   out_b, nullptr, nullptr,
                                   (float*)d_out, nullptr, nullptr, nullptr, nullptr,
                                   5, 0, 0);
}